// round 14
// baseline (speedup 1.0000x reference)
#include <cuda_runtime.h>
#include <cuda_bf16.h>
#include <cstdint>
#include <math.h>

// ---------------- problem constants ----------------
#define B_     64
#define HID_   2048
#define NH_    32
#define NKV_   8
#define HD_    64
#define G_     4          // NH/NKV
#define BS_    16
#define MAXB_  128
#define MAXKV_ 2048
#define QKVN_  3072       // NH*HD + 2*NKV*HD
#define SCALE_ 0.125f     // 64^-0.5
#define T_     32         // attention KV tile (positions)
#define SPLIT_ 8          // KV splits per (b, kv-head)
#define SCP_   264        // scs row stride (floats)
// GEMM tiling
#define ASTR   40         // A smem row stride (bf16)
#define BSTR   72         // B smem row stride (bf16)
#define GSPL   4          // GEMM K-splits

// ---------------- scratch: device globals only ----------------
__device__ float g_qkv [B_ * QKVN_];
__device__ float g_q   [B_ * NH_ * HD_];
__device__ float g_k   [B_ * NKV_ * HD_];
__device__ float g_att [B_ * NH_ * HD_];
__device__ float g_psum[B_ * NKV_ * SPLIT_ * G_];
__device__ float g_pout[B_ * NKV_ * SPLIT_ * G_ * HD_];
__device__ float g_part[GSPL * B_ * QKVN_];       // GEMM split partials (3MB max)
// bf16 hi/lo operands
__device__ __nv_bfloat16 g_ah[B_ * HID_];         // A hi [64][2048]
__device__ __nv_bfloat16 g_al[B_ * HID_];         // A lo
__device__ __nv_bfloat16 g_bh[HID_ * QKVN_];      // B hi [K][N] (row-major, like w)
__device__ __nv_bfloat16 g_bl[HID_ * QKVN_];      // B lo

// ---------------- cp.async helpers ----------------
__device__ __forceinline__ void cpa16(void* smem, const void* gptr) {
    unsigned a = (unsigned)__cvta_generic_to_shared(smem);
    asm volatile("cp.async.cg.shared.global [%0], [%1], 16;\n" :: "r"(a), "l"(gptr));
}
__device__ __forceinline__ void cpa16z(void* smem, const void* gptr, bool v) {
    unsigned a = (unsigned)__cvta_generic_to_shared(smem);
    int sz = v ? 16 : 0;
    asm volatile("cp.async.cg.shared.global [%0], [%1], 16, %2;\n"
                 :: "r"(a), "l"(gptr), "r"(sz));
}
#define CPA_COMMIT() asm volatile("cp.async.commit_group;\n")
#define CPA_WAIT0()  asm volatile("cp.async.wait_group 0;\n")
#define CPA_WAIT1()  asm volatile("cp.async.wait_group 1;\n")

// ---------------- mma.sync helpers (sm_80+, arch-agnostic) ----------------
__device__ __forceinline__ void ldsm_x4(unsigned* r, unsigned addr) {
    asm volatile("ldmatrix.sync.aligned.m8n8.x4.shared.b16 {%0,%1,%2,%3}, [%4];"
                 : "=r"(r[0]), "=r"(r[1]), "=r"(r[2]), "=r"(r[3]) : "r"(addr));
}
__device__ __forceinline__ void ldsm_x4t(unsigned* r, unsigned addr) {
    asm volatile("ldmatrix.sync.aligned.m8n8.x4.trans.shared.b16 {%0,%1,%2,%3}, [%4];"
                 : "=r"(r[0]), "=r"(r[1]), "=r"(r[2]), "=r"(r[3]) : "r"(addr));
}
__device__ __forceinline__ void mma_bf16(float* c, const unsigned* a, const unsigned* b) {
    asm volatile(
        "mma.sync.aligned.m16n8k16.row.col.f32.bf16.bf16.f32 "
        "{%0,%1,%2,%3}, {%4,%5,%6,%7}, {%8,%9}, {%0,%1,%2,%3};"
        : "+f"(c[0]), "+f"(c[1]), "+f"(c[2]), "+f"(c[3])
        : "r"(a[0]), "r"(a[1]), "r"(a[2]), "r"(a[3]), "r"(b[0]), "r"(b[1]));
}

// ============================================================================
// Conversion kernels
// ============================================================================
__device__ __forceinline__ void conv_a_body(const float* __restrict__ src) {
    int idx = blockIdx.x * 256 + threadIdx.x;      // 64*2048
    float v = src[idx];
    __nv_bfloat16 h = __float2bfloat16(v);
    g_ah[idx] = h;
    g_al[idx] = __float2bfloat16(v - __bfloat162float(h));
}
__global__ void conv_a_hidden(const float* __restrict__ a) { conv_a_body(a); }
__global__ void conv_a_att() { conv_a_body(g_att); }

__global__ void conv_b_kernel(const float* __restrict__ w, int total) {
    int idx = blockIdx.x * 256 + threadIdx.x;
    if (idx < total) {
        float v = w[idx];
        __nv_bfloat16 h = __float2bfloat16(v);
        g_bh[idx] = h;
        g_bl[idx] = __float2bfloat16(v - __bfloat162float(h));
    }
}

// ============================================================================
// mma.sync GEMM: part[split](64xN tile) = A(64xKchunk) * B(KchunkxN)
// BM64 BN64 BK32, 8 warps (4Mx2N), warp tile 16x32, bf16 hi/lo 3-pass.
// ============================================================================
__device__ __forceinline__ void gemm_mma_body(int N, int kb0, int nkb, int split)
{
    __shared__ __nv_bfloat16 sAh[2][64 * ASTR], sAl[2][64 * ASTR];   // 10KB ea pair
    __shared__ __nv_bfloat16 sBh[2][32 * BSTR], sBl[2][32 * BSTR];   // 9KB ea pair

    int n0 = blockIdx.x * 64;
    int t = threadIdx.x, lane = t & 31, wid = t >> 5;
    int m0 = (wid & 3) * 16, wn0 = (wid >> 2) * 32;

    float acc[4][4];
#pragma unroll
    for (int j = 0; j < 4; j++)
#pragma unroll
        for (int i = 0; i < 4; i++) acc[j][i] = 0.f;

    int ar = t >> 2, ac = t & 3;          // A loader: row, 16B col group
    int bk = t >> 3, bn = t & 7;          // B loader: k-row, 16B col group

    // ldmatrix per-lane addresses (element offsets; x2 for bytes)
    int lg = lane >> 3, lr = lane & 7;
    int a_row = m0 + (lg & 1) * 8 + lr, a_colb = (lg >> 1) * 8;
    int b_krow = (lg & 1) * 8 + lr, b_ncol = (lg >> 1) * 8;

#define LOAD_TILE(buf, kb) do { \
    cpa16(&sAh[buf][ar * ASTR + ac * 8], g_ah + (size_t)ar * HID_ + (kb) + ac * 8); \
    cpa16(&sAl[buf][ar * ASTR + ac * 8], g_al + (size_t)ar * HID_ + (kb) + ac * 8); \
    cpa16(&sBh[buf][bk * BSTR + bn * 8], g_bh + (size_t)((kb) + bk) * N + n0 + bn * 8); \
    cpa16(&sBl[buf][bk * BSTR + bn * 8], g_bl + (size_t)((kb) + bk) * N + n0 + bn * 8); \
} while (0)

    LOAD_TILE(0, kb0);
    CPA_COMMIT();

    for (int kt = 0; kt < nkb; kt++) {
        int buf = kt & 1;
        if (kt + 1 < nkb) {
            LOAD_TILE(buf ^ 1, kb0 + (kt + 1) * 32);
            CPA_COMMIT();
            CPA_WAIT1();
        } else {
            CPA_WAIT0();
        }
        __syncthreads();
#pragma unroll
        for (int ks = 0; ks < 2; ks++) {
            unsigned ah4[4], al4[4], bh4[2][4], bl4[2][4];
            unsigned aoff = (unsigned)((a_row * ASTR + ks * 16 + a_colb) * 2);
            ldsm_x4(ah4, (unsigned)__cvta_generic_to_shared(&sAh[buf][0]) + aoff);
            ldsm_x4(al4, (unsigned)__cvta_generic_to_shared(&sAl[buf][0]) + aoff);
#pragma unroll
            for (int nh = 0; nh < 2; nh++) {
                unsigned boff = (unsigned)(((ks * 16 + b_krow) * BSTR + wn0 + nh * 16 + b_ncol) * 2);
                ldsm_x4t(bh4[nh], (unsigned)__cvta_generic_to_shared(&sBh[buf][0]) + boff);
                ldsm_x4t(bl4[nh], (unsigned)__cvta_generic_to_shared(&sBl[buf][0]) + boff);
            }
#pragma unroll
            for (int j = 0; j < 4; j++) {
                const unsigned* bh = &bh4[j >> 1][(j & 1) * 2];
                const unsigned* bl = &bl4[j >> 1][(j & 1) * 2];
                mma_bf16(acc[j], ah4, bh);
                mma_bf16(acc[j], al4, bh);
                mma_bf16(acc[j], ah4, bl);
            }
        }
        __syncthreads();
    }

    // epilogue: c0,c1 -> (row gid, col 2q..2q+1); c2,c3 -> (row gid+8)
    int gid = lane >> 2, q = lane & 3;
    float* dst = g_part + (size_t)split * (64 * N);
#pragma unroll
    for (int j = 0; j < 4; j++) {
        int col = n0 + wn0 + j * 8 + q * 2;
        int row0 = m0 + gid;
        *(float2*)&dst[(size_t)row0 * N + col]       = make_float2(acc[j][0], acc[j][1]);
        *(float2*)&dst[(size_t)(row0 + 8) * N + col] = make_float2(acc[j][2], acc[j][3]);
    }
#undef LOAD_TILE
}

__global__ __launch_bounds__(256) void gemm_mma_qkv() {
    gemm_mma_body(QKVN_, blockIdx.y * (HID_ / GSPL), (HID_ / GSPL) / 32, blockIdx.y);
}
__global__ __launch_bounds__(256) void gemm_mma_out() {
    gemm_mma_body(HID_, blockIdx.y * (HID_ / GSPL), (HID_ / GSPL) / 32, blockIdx.y);
}

// ---------------- split reductions (float4, GSPL=4) ----------------
__global__ void reduce_qkv_kernel() {
    int i = blockIdx.x * 256 + threadIdx.x;    // n4 = 49152
    const float4* p = (const float4*)g_part;
    float4 s = p[i];
#pragma unroll
    for (int k = 1; k < GSPL; k++) {
        float4 v = p[(size_t)k * 49152 + i];
        s.x += v.x; s.y += v.y; s.z += v.z; s.w += v.w;
    }
    ((float4*)g_qkv)[i] = s;
}
__global__ void reduce_out_kernel(float* __restrict__ out) {
    int i = blockIdx.x * 256 + threadIdx.x;    // n4 = 32768
    const float4* p = (const float4*)g_part;
    float4 s = p[i];
#pragma unroll
    for (int k = 1; k < GSPL; k++) {
        float4 v = p[(size_t)k * 32768 + i];
        s.x += v.x; s.y += v.y; s.z += v.z; s.w += v.w;
    }
    ((float4*)out)[i] = s;
}

// ---------------- RMSNorm + RoPE ----------------
__global__ __launch_bounds__(256) void prep_kernel(
    const int* __restrict__ positions,
    const float* __restrict__ qw, const float* __restrict__ kw)
{
    int b = blockIdx.x;
    int t = threadIdx.x, w = t >> 5, lane = t & 31;
    __shared__ float cs[32], sn[32];

    int pos = positions[b];
    if (t < 32) {
        double v = 1.0;
        if (t & 1)  v *= 0.6493816315762113;
        if (t & 2)  v *= 0.4216965034285822;
        if (t & 4)  v *= 0.17782794100389228;
        if (t & 8)  v *= 0.03162277660168379;
        if (t & 16) v *= 0.001;
        double ang = (double)pos * v;
        double k = floor(ang * 0.15915494309189535);
        float r = (float)(ang - k * 6.283185307179586);
        cs[t] = cosf(r);
        sn[t] = sinf(r);
    }
    __syncthreads();

    const float* row = g_qkv + (size_t)b * QKVN_;
    for (int h = w; h < NH_ + NKV_; h += 8) {
        bool isq = (h < NH_);
        const float* src = isq ? row + h * HD_ : row + NH_ * HD_ + (h - NH_) * HD_;
        float x1 = src[lane], x2 = src[lane + 32];
        float ss = x1 * x1 + x2 * x2;
#pragma unroll
        for (int o = 16; o; o >>= 1) ss += __shfl_xor_sync(0xffffffffu, ss, o);
        float inv = rsqrtf(ss * (1.f / 64.f) + 1e-5f);
        const float* lw = isq ? qw : kw;
        x1 *= inv * lw[lane];
        x2 *= inv * lw[lane + 32];
        float c = cs[lane], s = sn[lane];
        float y1 = x1 * c - x2 * s;
        float y2 = x2 * c + x1 * s;
        float* dst = isq ? g_q + ((size_t)b * NH_ + h) * HD_
                         : g_k + ((size_t)b * NKV_ + (h - NH_)) * HD_;
        dst[lane]      = y1;
        dst[lane + 32] = y2;
    }
}

// ============================================================================
// Split-KV attention (shift-free softmax; |score| <= 8 by rmsnorm bound).
// ============================================================================
__device__ __forceinline__ void tile_load(
    float* dst, const float* __restrict__ cache, const float* __restrict__ newrow,
    const int* sbt, int kv, int s0, int send, int ctx, int t)
{
    int c = t & 15;
#pragma unroll
    for (int r = 0; r < 2; r++) {
        int p = (t >> 4) + 16 * r;
        int s = s0 + p;
        bool v = (s < send);
        const float* src = cache;
        if (v) {
            if (s == ctx - 1) src = newrow + c * 4;
            else {
                int blk = sbt[s >> 4];
                src = cache + (((size_t)blk * BS_ + (s & 15)) * NKV_ + kv) * HD_ + c * 4;
            }
        }
        cpa16z(dst + p * 64 + c * 4, src, v);
    }
}

__global__ __launch_bounds__(256) void attn_split_kernel(
    const float* __restrict__ kc, const float* __restrict__ vc,
    const int* __restrict__ ctxlens, const int* __restrict__ btab)
{
    __shared__ float kt[3][T_ * 64];
    __shared__ float scs[G_ * SCP_];
    __shared__ float aux[1024];
    __shared__ float redm[8][4];
    __shared__ int   sbt[MAXB_];

    int kv = blockIdx.x, b = blockIdx.y, sp = blockIdx.z;
    int t = threadIdx.x, w = t >> 5, lane = t & 31;
    int ctx = ctxlens[b];
    ctx = ctx < 1 ? 1 : (ctx > MAXKV_ ? MAXKV_ : ctx);

    int chunk = (ctx + SPLIT_ - 1) / SPLIT_;
    int c0 = sp * chunk;
    int cn = min(chunk, ctx - c0);
    int pbase = ((b * NKV_ + kv) * SPLIT_ + sp) * G_;

    if (cn <= 0) {
        if (t < G_) g_psum[pbase + t] = 0.f;
        g_pout[(size_t)(pbase + (t >> 6)) * HD_ + (t & 63)] = 0.f;
        return;
    }

    if (t < MAXB_) sbt[t] = btab[b * MAXB_ + t];

    const float* knew_p = g_k + ((size_t)b * NKV_ + kv) * HD_;
    const float* vnew_p = g_qkv + (size_t)b * QKVN_ + NH_ * HD_ + NKV_ * HD_ + kv * HD_;

    int p = t >> 3, oct = t & 7;
    int g = (oct & 1) * 2 + ((oct >> 1) & 1);
    float4 qA[4], qB[4];
#pragma unroll
    for (int gg = 0; gg < 4; gg++) {
        const float* qrow = g_q + ((size_t)b * NH_ + kv * G_ + gg) * HD_;
        qA[gg] = *(const float4*)(qrow + oct * 4);
        qB[gg] = *(const float4*)(qrow + (oct + 8) * 4);
    }
    __syncthreads();

    int send = c0 + cn;
    int ntiles = (cn + T_ - 1) / T_;
    float sum_loc = 0.f;

    // ---- pass 1: probs = exp(q.K * scale) ----
#pragma unroll
    for (int i = 0; i < 2; i++) {
        if (i < ntiles) tile_load(kt[i], kc, knew_p, sbt, kv, c0 + i * T_, send, ctx, t);
        CPA_COMMIT();
    }
    for (int j = 0; j < ntiles; j++) {
        if (j < ntiles - 1) CPA_WAIT1(); else CPA_WAIT0();
        __syncthreads();
        if (j + 2 < ntiles) {
            tile_load(kt[(j + 2) % 3], kc, knew_p, sbt, kv, c0 + (j + 2) * T_, send, ctx, t);
            CPA_COMMIT();
        }
        const float* kb = kt[j % 3] + p * 64;
        float4 kA = *(const float4*)(kb + oct * 4);
        float4 kB = *(const float4*)(kb + (oct + 8) * 4);
        float dots[4];
#pragma unroll
        for (int gg = 0; gg < 4; gg++) {
            dots[gg] = qA[gg].x * kA.x + qA[gg].y * kA.y + qA[gg].z * kA.z + qA[gg].w * kA.w
                     + qB[gg].x * kB.x + qB[gg].y * kB.y + qB[gg].z * kB.z + qB[gg].w * kB.w;
        }
        bool b0 = oct & 1, b1 = oct & 2;
        float s1 = b0 ? dots[0] : dots[2];
        float r1 = __shfl_xor_sync(0xffffffffu, s1, 1);
        if (!b0) dots[0] += r1; else dots[2] += r1;
        float s2 = b0 ? dots[1] : dots[3];
        float r2 = __shfl_xor_sync(0xffffffffu, s2, 1);
        if (!b0) dots[1] += r2; else dots[3] += r2;
        float v0 = b0 ? dots[2] : dots[0];
        float v1 = b0 ? dots[3] : dots[1];
        float s3 = b1 ? v0 : v1;
        float r3 = __shfl_xor_sync(0xffffffffu, s3, 2);
        float v = (b1 ? v1 : v0) + r3;
        v += __shfl_xor_sync(0xffffffffu, v, 4);
        int sl = j * T_ + p;
        float pe = (sl < cn) ? __expf(v * SCALE_) : 0.f;
        if (oct < 4) scs[g * SCP_ + sl] = pe;
        sum_loc += pe;
    }
    sum_loc += __shfl_xor_sync(0xffffffffu, sum_loc, 8);
    sum_loc += __shfl_xor_sync(0xffffffffu, sum_loc, 16);
    if (lane < 4) redm[w][g] = sum_loc;
    __syncthreads();
    if (t < G_) {
        float ss = 0.f;
#pragma unroll
        for (int ww = 0; ww < 8; ww++) ss += redm[ww][t];
        g_psum[pbase + t] = ss;
    }
    __syncthreads();

    // ---- pass 2: out[g][d] = sum_s p[g][s] * V[s][d] ----
    int d = t & 63, sg = t >> 6;
    float oa0 = 0.f, oa1 = 0.f, oa2 = 0.f, oa3 = 0.f;
#pragma unroll
    for (int i = 0; i < 2; i++) {
        if (i < ntiles) tile_load(kt[i], vc, vnew_p, sbt, kv, c0 + i * T_, send, ctx, t);
        CPA_COMMIT();
    }
    for (int j = 0; j < ntiles; j++) {
        if (j < ntiles - 1) CPA_WAIT1(); else CPA_WAIT0();
        __syncthreads();
        if (j + 2 < ntiles) {
            tile_load(kt[(j + 2) % 3], vc, vnew_p, sbt, kv, c0 + (j + 2) * T_, send, ctx, t);
            CPA_COMMIT();
        }
        const float* vb = kt[j % 3];
        const float4* s4 = (const float4*)scs;
        int f0 = j * 8 + sg * 2;
#pragma unroll
        for (int i = 0; i < 2; i++) {
            float4 pa = s4[0 * 66 + f0 + i];
            float4 pb = s4[1 * 66 + f0 + i];
            float4 pc = s4[2 * 66 + f0 + i];
            float4 pd = s4[3 * 66 + f0 + i];
            int sb = (sg * 8 + i * 4) * 64 + d;
            float w0 = vb[sb], w1 = vb[sb + 64], w2 = vb[sb + 128], w3 = vb[sb + 192];
            oa0 += pa.x * w0 + pa.y * w1 + pa.z * w2 + pa.w * w3;
            oa1 += pb.x * w0 + pb.y * w1 + pb.z * w2 + pb.w * w3;
            oa2 += pc.x * w0 + pc.y * w1 + pc.z * w2 + pc.w * w3;
            oa3 += pd.x * w0 + pd.y * w1 + pd.z * w2 + pd.w * w3;
        }
    }
    __syncthreads();
    aux[sg * 256 + 0 * 64 + d] = oa0;
    aux[sg * 256 + 1 * 64 + d] = oa1;
    aux[sg * 256 + 2 * 64 + d] = oa2;
    aux[sg * 256 + 3 * 64 + d] = oa3;
    __syncthreads();
    {
        int g2 = t >> 6, d2 = t & 63;
        float oo = aux[0 * 256 + g2 * 64 + d2] + aux[1 * 256 + g2 * 64 + d2]
                 + aux[2 * 256 + g2 * 64 + d2] + aux[3 * 256 + g2 * 64 + d2];
        g_pout[(size_t)(pbase + g2) * HD_ + d2] = oo;
    }
}

// ---------------- combine splits: plain sums ----------------
__global__ __launch_bounds__(256) void attn_combine_kernel()
{
    int kv = blockIdx.x, b = blockIdx.y;
    int t = threadIdx.x, g = t >> 6, d = t & 63;
    int base = (b * NKV_ + kv) * SPLIT_ * G_;

    float denom = 0.f, numer = 0.f;
#pragma unroll
    for (int i = 0; i < SPLIT_; i++) {
        denom += g_psum[base + i * G_ + g];
        numer += g_pout[(size_t)(base + i * G_ + g) * HD_ + d];
    }
    g_att[(size_t)b * (NH_ * HD_) + (kv * G_ + g) * HD_ + d] = numer / denom;
}

// ---------------- launch: kernel launches ONLY ----------------
extern "C" void kernel_launch(void* const* d_in, const int* in_sizes, int n_in,
                              void* d_out, int out_size)
{
    const float* hidden    = (const float*)d_in[0];
    const int*   positions = (const int*)  d_in[1];
    const int*   ctxlens   = (const int*)  d_in[2];
    // d_in[3] slot_mapping unused: phys(ctx-1) == slot, new k/v read directly
    const int*   btab      = (const int*)  d_in[4];
    const float* kc        = (const float*)d_in[5];
    const float* vc        = (const float*)d_in[6];
    const float* wqkv      = (const float*)d_in[7];
    const float* wout      = (const float*)d_in[8];
    const float* qlw       = (const float*)d_in[9];
    const float* klw       = (const float*)d_in[10];
    float* out = (float*)d_out;

    conv_a_hidden<<<B_ * HID_ / 256, 256>>>(hidden);
    conv_b_kernel<<<HID_ * QKVN_ / 256, 256>>>(wqkv, HID_ * QKVN_);
    gemm_mma_qkv<<<dim3(QKVN_ / 64, GSPL), 256>>>();
    reduce_qkv_kernel<<<192, 256>>>();
    prep_kernel<<<B_, 256>>>(positions, qlw, klw);
    attn_split_kernel<<<dim3(NKV_, B_, SPLIT_), 256>>>(kc, vc, ctxlens, btab);
    attn_combine_kernel<<<dim3(NKV_, B_), 256>>>();
    conv_a_att<<<B_ * HID_ / 256, 256>>>();
    conv_b_kernel<<<HID_ * HID_ / 256, 256>>>(wout, HID_ * HID_);
    gemm_mma_out<<<dim3(HID_ / 64, GSPL), 256>>>();
    reduce_out_kernel<<<128, 256>>>(out);
}

// round 15
// speedup vs baseline: 1.1746x; 1.1746x over previous
#include <cuda_runtime.h>
#include <cuda_bf16.h>
#include <cstdint>
#include <math.h>

// ---------------- problem constants ----------------
#define B_     64
#define HID_   2048
#define NH_    32
#define NKV_   8
#define HD_    64
#define G_     4          // NH/NKV
#define BS_    16
#define MAXB_  128
#define MAXKV_ 2048
#define QKVN_  3072       // NH*HD + 2*NKV*HD
#define SCALE_ 0.125f     // 64^-0.5
#define T_     32         // attention KV tile (positions)
#define SPLIT_ 8          // KV splits per (b, kv-head)
#define SCP_   264        // scs row stride (floats)
// GEMM tiling
#define ASTR   40         // A smem row stride (bf16)
#define BSTR   72         // B smem row stride (bf16)
#define GSPL   4          // GEMM K-splits

// ---------------- scratch: device globals only ----------------
__device__ float g_qkv [B_ * QKVN_];
__device__ float g_q   [B_ * NH_ * HD_];
__device__ float g_k   [B_ * NKV_ * HD_];
__device__ float g_att [B_ * NH_ * HD_];
__device__ float g_psum[B_ * NKV_ * SPLIT_ * G_];
__device__ float g_pout[B_ * NKV_ * SPLIT_ * G_ * HD_];
__device__ float g_part[GSPL * B_ * QKVN_];       // GEMM split partials (3MB max)
__device__ __nv_bfloat16 g_ah[B_ * HID_];         // A hi [64][2048]
__device__ __nv_bfloat16 g_al[B_ * HID_];         // A lo

// ---------------- cp.async helpers ----------------
__device__ __forceinline__ void cpa16(void* smem, const void* gptr) {
    unsigned a = (unsigned)__cvta_generic_to_shared(smem);
    asm volatile("cp.async.cg.shared.global [%0], [%1], 16;\n" :: "r"(a), "l"(gptr));
}
__device__ __forceinline__ void cpa16z(void* smem, const void* gptr, bool v) {
    unsigned a = (unsigned)__cvta_generic_to_shared(smem);
    int sz = v ? 16 : 0;
    asm volatile("cp.async.cg.shared.global [%0], [%1], 16, %2;\n"
                 :: "r"(a), "l"(gptr), "r"(sz));
}
#define CPA_COMMIT() asm volatile("cp.async.commit_group;\n")
#define CPA_WAIT0()  asm volatile("cp.async.wait_group 0;\n")
#define CPA_WAIT1()  asm volatile("cp.async.wait_group 1;\n")

// ---------------- mma.sync helpers (sm_80+, arch-agnostic) ----------------
__device__ __forceinline__ void ldsm_x4(unsigned* r, unsigned addr) {
    asm volatile("ldmatrix.sync.aligned.m8n8.x4.shared.b16 {%0,%1,%2,%3}, [%4];"
                 : "=r"(r[0]), "=r"(r[1]), "=r"(r[2]), "=r"(r[3]) : "r"(addr));
}
__device__ __forceinline__ void ldsm_x4t(unsigned* r, unsigned addr) {
    asm volatile("ldmatrix.sync.aligned.m8n8.x4.trans.shared.b16 {%0,%1,%2,%3}, [%4];"
                 : "=r"(r[0]), "=r"(r[1]), "=r"(r[2]), "=r"(r[3]) : "r"(addr));
}
__device__ __forceinline__ void mma_bf16(float* c, const unsigned* a, const unsigned* b) {
    asm volatile(
        "mma.sync.aligned.m16n8k16.row.col.f32.bf16.bf16.f32 "
        "{%0,%1,%2,%3}, {%4,%5,%6,%7}, {%8,%9}, {%0,%1,%2,%3};"
        : "+f"(c[0]), "+f"(c[1]), "+f"(c[2]), "+f"(c[3])
        : "r"(a[0]), "r"(a[1]), "r"(a[2]), "r"(a[3]), "r"(b[0]), "r"(b[1]));
}

// ============================================================================
// A conversion (tiny: 64x2048)
// ============================================================================
__device__ __forceinline__ void conv_a_body(const float* __restrict__ src) {
    int idx = blockIdx.x * 256 + threadIdx.x;
    float v = src[idx];
    __nv_bfloat16 h = __float2bfloat16(v);
    g_ah[idx] = h;
    g_al[idx] = __float2bfloat16(v - __bfloat162float(h));
}
__global__ void conv_a_hidden(const float* __restrict__ a) { conv_a_body(a); }
__global__ void conv_a_att() { conv_a_body(g_att); }

// ============================================================================
// mma.sync GEMM with FUSED weight conversion:
// part[split](64xN tile) = A(64xKchunk) * w(KchunkxN)
// BM64 BN64 BK32, 8 warps (4Mx2N), bf16 hi/lo 3-pass. w read once as fp32.
// ============================================================================
__device__ __forceinline__ void gemm_mma_body(
    const float* __restrict__ w, int N, int kb0, int nkb, int split)
{
    __shared__ __nv_bfloat16 sAh[2][64 * ASTR], sAl[2][64 * ASTR];   // 20.5KB
    __shared__ __nv_bfloat16 sBh[32 * BSTR], sBl[32 * BSTR];         // 9.2KB

    int n0 = blockIdx.x * 64;
    int t = threadIdx.x, lane = t & 31, wid = t >> 5;
    int m0 = (wid & 3) * 16, wn0 = (wid >> 2) * 32;

    float acc[4][4];
#pragma unroll
    for (int j = 0; j < 4; j++)
#pragma unroll
        for (int i = 0; i < 4; i++) acc[j][i] = 0.f;

    int ar = t >> 2, ac = t & 3;          // A loader: row, 16B col group
    int br = t >> 3, bc = (t & 7) * 8;    // B loader: k-row 0..31, col 0..56

    // ldmatrix per-lane addresses
    int lg = lane >> 3, lr = lane & 7;
    int a_row = m0 + (lg & 1) * 8 + lr, a_colb = (lg >> 1) * 8;
    int b_krow = (lg & 1) * 8 + lr, b_ncol = (lg >> 1) * 8;

#define LOAD_A(buf, kb) do { \
    cpa16(&sAh[buf][ar * ASTR + ac * 8], g_ah + (size_t)ar * HID_ + (kb) + ac * 8); \
    cpa16(&sAl[buf][ar * ASTR + ac * 8], g_al + (size_t)ar * HID_ + (kb) + ac * 8); \
} while (0)

    float4 breg0, breg1;
#define LDGB(kb) do { \
    const float* wp = w + (size_t)((kb) + br) * N + n0 + bc; \
    breg0 = *(const float4*)wp; breg1 = *(const float4*)(wp + 4); \
} while (0)

    LOAD_A(0, kb0);
    CPA_COMMIT();
    LDGB(kb0);

    for (int kt = 0; kt < nkb; kt++) {
        int buf = kt & 1;
        if (kt + 1 < nkb) {
            LOAD_A(buf ^ 1, kb0 + (kt + 1) * 32);
            CPA_COMMIT();
            CPA_WAIT1();
        } else {
            CPA_WAIT0();
        }
        // convert current B regs -> smem (hi/lo), STS.128
        {
            float vals[8] = {breg0.x, breg0.y, breg0.z, breg0.w,
                             breg1.x, breg1.y, breg1.z, breg1.w};
            __nv_bfloat16 th[8], tl[8];
#pragma unroll
            for (int i = 0; i < 8; i++) {
                __nv_bfloat16 h = __float2bfloat16(vals[i]);
                th[i] = h;
                tl[i] = __float2bfloat16(vals[i] - __bfloat162float(h));
            }
            *(uint4*)&sBh[br * BSTR + bc] = *(uint4*)th;
            *(uint4*)&sBl[br * BSTR + bc] = *(uint4*)tl;
        }
        __syncthreads();
        if (kt + 1 < nkb) LDGB(kb0 + (kt + 1) * 32);   // overlap with mma
#pragma unroll
        for (int ks = 0; ks < 2; ks++) {
            unsigned ah4[4], al4[4], bh4[2][4], bl4[2][4];
            unsigned aoff = (unsigned)((a_row * ASTR + ks * 16 + a_colb) * 2);
            ldsm_x4(ah4, (unsigned)__cvta_generic_to_shared(&sAh[buf][0]) + aoff);
            ldsm_x4(al4, (unsigned)__cvta_generic_to_shared(&sAl[buf][0]) + aoff);
#pragma unroll
            for (int nh = 0; nh < 2; nh++) {
                unsigned boff = (unsigned)(((ks * 16 + b_krow) * BSTR + wn0 + nh * 16 + b_ncol) * 2);
                ldsm_x4t(bh4[nh], (unsigned)__cvta_generic_to_shared(&sBh[0]) + boff);
                ldsm_x4t(bl4[nh], (unsigned)__cvta_generic_to_shared(&sBl[0]) + boff);
            }
#pragma unroll
            for (int j = 0; j < 4; j++) {
                const unsigned* bh = &bh4[j >> 1][(j & 1) * 2];
                const unsigned* bl = &bl4[j >> 1][(j & 1) * 2];
                mma_bf16(acc[j], ah4, bh);
                mma_bf16(acc[j], al4, bh);
                mma_bf16(acc[j], ah4, bl);
            }
        }
        __syncthreads();
    }

    int gid = lane >> 2, q = lane & 3;
    float* dst = g_part + (size_t)split * (64 * N);
#pragma unroll
    for (int j = 0; j < 4; j++) {
        int col = n0 + wn0 + j * 8 + q * 2;
        int row0 = m0 + gid;
        *(float2*)&dst[(size_t)row0 * N + col]       = make_float2(acc[j][0], acc[j][1]);
        *(float2*)&dst[(size_t)(row0 + 8) * N + col] = make_float2(acc[j][2], acc[j][3]);
    }
#undef LOAD_A
#undef LDGB
}

__global__ __launch_bounds__(256) void gemm_mma_qkv(const float* __restrict__ w) {
    gemm_mma_body(w, QKVN_, blockIdx.y * (HID_ / GSPL), (HID_ / GSPL) / 32, blockIdx.y);
}
__global__ __launch_bounds__(256) void gemm_mma_out(const float* __restrict__ w) {
    gemm_mma_body(w, HID_, blockIdx.y * (HID_ / GSPL), (HID_ / GSPL) / 32, blockIdx.y);
}

// ---------------- split reductions (float4, GSPL=4) ----------------
__global__ void reduce_qkv_kernel() {
    int i = blockIdx.x * 256 + threadIdx.x;    // n4 = 49152
    const float4* p = (const float4*)g_part;
    float4 s = p[i];
#pragma unroll
    for (int k = 1; k < GSPL; k++) {
        float4 v = p[(size_t)k * 49152 + i];
        s.x += v.x; s.y += v.y; s.z += v.z; s.w += v.w;
    }
    ((float4*)g_qkv)[i] = s;
}
__global__ void reduce_out_kernel(float* __restrict__ out) {
    int i = blockIdx.x * 256 + threadIdx.x;    // n4 = 32768
    const float4* p = (const float4*)g_part;
    float4 s = p[i];
#pragma unroll
    for (int k = 1; k < GSPL; k++) {
        float4 v = p[(size_t)k * 32768 + i];
        s.x += v.x; s.y += v.y; s.z += v.z; s.w += v.w;
    }
    ((float4*)out)[i] = s;
}

// ---------------- RMSNorm + RoPE ----------------
__global__ __launch_bounds__(256) void prep_kernel(
    const int* __restrict__ positions,
    const float* __restrict__ qw, const float* __restrict__ kw)
{
    int b = blockIdx.x;
    int t = threadIdx.x, w = t >> 5, lane = t & 31;
    __shared__ float cs[32], sn[32];

    int pos = positions[b];
    if (t < 32) {
        double v = 1.0;
        if (t & 1)  v *= 0.6493816315762113;
        if (t & 2)  v *= 0.4216965034285822;
        if (t & 4)  v *= 0.17782794100389228;
        if (t & 8)  v *= 0.03162277660168379;
        if (t & 16) v *= 0.001;
        double ang = (double)pos * v;
        double k = floor(ang * 0.15915494309189535);
        float r = (float)(ang - k * 6.283185307179586);
        cs[t] = cosf(r);
        sn[t] = sinf(r);
    }
    __syncthreads();

    const float* row = g_qkv + (size_t)b * QKVN_;
    for (int h = w; h < NH_ + NKV_; h += 8) {
        bool isq = (h < NH_);
        const float* src = isq ? row + h * HD_ : row + NH_ * HD_ + (h - NH_) * HD_;
        float x1 = src[lane], x2 = src[lane + 32];
        float ss = x1 * x1 + x2 * x2;
#pragma unroll
        for (int o = 16; o; o >>= 1) ss += __shfl_xor_sync(0xffffffffu, ss, o);
        float inv = rsqrtf(ss * (1.f / 64.f) + 1e-5f);
        const float* lw = isq ? qw : kw;
        x1 *= inv * lw[lane];
        x2 *= inv * lw[lane + 32];
        float c = cs[lane], s = sn[lane];
        float y1 = x1 * c - x2 * s;
        float y2 = x2 * c + x1 * s;
        float* dst = isq ? g_q + ((size_t)b * NH_ + h) * HD_
                         : g_k + ((size_t)b * NKV_ + (h - NH_)) * HD_;
        dst[lane]      = y1;
        dst[lane + 32] = y2;
    }
}

// ============================================================================
// Split-KV attention (shift-free softmax; |score| <= 8 by rmsnorm bound).
// ============================================================================
__device__ __forceinline__ void tile_load(
    float* dst, const float* __restrict__ cache, const float* __restrict__ newrow,
    const int* sbt, int kv, int s0, int send, int ctx, int t)
{
    int c = t & 15;
#pragma unroll
    for (int r = 0; r < 2; r++) {
        int p = (t >> 4) + 16 * r;
        int s = s0 + p;
        bool v = (s < send);
        const float* src = cache;
        if (v) {
            if (s == ctx - 1) src = newrow + c * 4;
            else {
                int blk = sbt[s >> 4];
                src = cache + (((size_t)blk * BS_ + (s & 15)) * NKV_ + kv) * HD_ + c * 4;
            }
        }
        cpa16z(dst + p * 64 + c * 4, src, v);
    }
}

__global__ __launch_bounds__(256) void attn_split_kernel(
    const float* __restrict__ kc, const float* __restrict__ vc,
    const int* __restrict__ ctxlens, const int* __restrict__ btab)
{
    __shared__ float kt[3][T_ * 64];
    __shared__ float scs[G_ * SCP_];
    __shared__ float aux[1024];
    __shared__ float redm[8][4];
    __shared__ int   sbt[MAXB_];

    int kv = blockIdx.x, b = blockIdx.y, sp = blockIdx.z;
    int t = threadIdx.x, w = t >> 5, lane = t & 31;
    int ctx = ctxlens[b];
    ctx = ctx < 1 ? 1 : (ctx > MAXKV_ ? MAXKV_ : ctx);

    int chunk = (ctx + SPLIT_ - 1) / SPLIT_;
    int c0 = sp * chunk;
    int cn = min(chunk, ctx - c0);
    int pbase = ((b * NKV_ + kv) * SPLIT_ + sp) * G_;

    if (cn <= 0) {
        if (t < G_) g_psum[pbase + t] = 0.f;
        g_pout[(size_t)(pbase + (t >> 6)) * HD_ + (t & 63)] = 0.f;
        return;
    }

    if (t < MAXB_) sbt[t] = btab[b * MAXB_ + t];

    const float* knew_p = g_k + ((size_t)b * NKV_ + kv) * HD_;
    const float* vnew_p = g_qkv + (size_t)b * QKVN_ + NH_ * HD_ + NKV_ * HD_ + kv * HD_;

    int p = t >> 3, oct = t & 7;
    int g = (oct & 1) * 2 + ((oct >> 1) & 1);
    float4 qA[4], qB[4];
#pragma unroll
    for (int gg = 0; gg < 4; gg++) {
        const float* qrow = g_q + ((size_t)b * NH_ + kv * G_ + gg) * HD_;
        qA[gg] = *(const float4*)(qrow + oct * 4);
        qB[gg] = *(const float4*)(qrow + (oct + 8) * 4);
    }
    __syncthreads();

    int send = c0 + cn;
    int ntiles = (cn + T_ - 1) / T_;
    float sum_loc = 0.f;

    // ---- pass 1: probs = exp(q.K * scale) ----
#pragma unroll
    for (int i = 0; i < 2; i++) {
        if (i < ntiles) tile_load(kt[i], kc, knew_p, sbt, kv, c0 + i * T_, send, ctx, t);
        CPA_COMMIT();
    }
    for (int j = 0; j < ntiles; j++) {
        if (j < ntiles - 1) CPA_WAIT1(); else CPA_WAIT0();
        __syncthreads();
        if (j + 2 < ntiles) {
            tile_load(kt[(j + 2) % 3], kc, knew_p, sbt, kv, c0 + (j + 2) * T_, send, ctx, t);
            CPA_COMMIT();
        }
        const float* kb = kt[j % 3] + p * 64;
        float4 kA = *(const float4*)(kb + oct * 4);
        float4 kB = *(const float4*)(kb + (oct + 8) * 4);
        float dots[4];
#pragma unroll
        for (int gg = 0; gg < 4; gg++) {
            dots[gg] = qA[gg].x * kA.x + qA[gg].y * kA.y + qA[gg].z * kA.z + qA[gg].w * kA.w
                     + qB[gg].x * kB.x + qB[gg].y * kB.y + qB[gg].z * kB.z + qB[gg].w * kB.w;
        }
        bool b0 = oct & 1, b1 = oct & 2;
        float s1 = b0 ? dots[0] : dots[2];
        float r1 = __shfl_xor_sync(0xffffffffu, s1, 1);
        if (!b0) dots[0] += r1; else dots[2] += r1;
        float s2 = b0 ? dots[1] : dots[3];
        float r2 = __shfl_xor_sync(0xffffffffu, s2, 1);
        if (!b0) dots[1] += r2; else dots[3] += r2;
        float v0 = b0 ? dots[2] : dots[0];
        float v1 = b0 ? dots[3] : dots[1];
        float s3 = b1 ? v0 : v1;
        float r3 = __shfl_xor_sync(0xffffffffu, s3, 2);
        float v = (b1 ? v1 : v0) + r3;
        v += __shfl_xor_sync(0xffffffffu, v, 4);
        int sl = j * T_ + p;
        float pe = (sl < cn) ? __expf(v * SCALE_) : 0.f;
        if (oct < 4) scs[g * SCP_ + sl] = pe;
        sum_loc += pe;
    }
    sum_loc += __shfl_xor_sync(0xffffffffu, sum_loc, 8);
    sum_loc += __shfl_xor_sync(0xffffffffu, sum_loc, 16);
    if (lane < 4) redm[w][g] = sum_loc;
    __syncthreads();
    if (t < G_) {
        float ss = 0.f;
#pragma unroll
        for (int ww = 0; ww < 8; ww++) ss += redm[ww][t];
        g_psum[pbase + t] = ss;
    }
    __syncthreads();

    // ---- pass 2: out[g][d] = sum_s p[g][s] * V[s][d] ----
    int d = t & 63, sg = t >> 6;
    float oa0 = 0.f, oa1 = 0.f, oa2 = 0.f, oa3 = 0.f;
#pragma unroll
    for (int i = 0; i < 2; i++) {
        if (i < ntiles) tile_load(kt[i], vc, vnew_p, sbt, kv, c0 + i * T_, send, ctx, t);
        CPA_COMMIT();
    }
    for (int j = 0; j < ntiles; j++) {
        if (j < ntiles - 1) CPA_WAIT1(); else CPA_WAIT0();
        __syncthreads();
        if (j + 2 < ntiles) {
            tile_load(kt[(j + 2) % 3], vc, vnew_p, sbt, kv, c0 + (j + 2) * T_, send, ctx, t);
            CPA_COMMIT();
        }
        const float* vb = kt[j % 3];
        const float4* s4 = (const float4*)scs;
        int f0 = j * 8 + sg * 2;
#pragma unroll
        for (int i = 0; i < 2; i++) {
            float4 pa = s4[0 * 66 + f0 + i];
            float4 pb = s4[1 * 66 + f0 + i];
            float4 pc = s4[2 * 66 + f0 + i];
            float4 pd = s4[3 * 66 + f0 + i];
            int sb = (sg * 8 + i * 4) * 64 + d;
            float w0 = vb[sb], w1 = vb[sb + 64], w2 = vb[sb + 128], w3 = vb[sb + 192];
            oa0 += pa.x * w0 + pa.y * w1 + pa.z * w2 + pa.w * w3;
            oa1 += pb.x * w0 + pb.y * w1 + pb.z * w2 + pb.w * w3;
            oa2 += pc.x * w0 + pc.y * w1 + pc.z * w2 + pc.w * w3;
            oa3 += pd.x * w0 + pd.y * w1 + pd.z * w2 + pd.w * w3;
        }
    }
    __syncthreads();
    aux[sg * 256 + 0 * 64 + d] = oa0;
    aux[sg * 256 + 1 * 64 + d] = oa1;
    aux[sg * 256 + 2 * 64 + d] = oa2;
    aux[sg * 256 + 3 * 64 + d] = oa3;
    __syncthreads();
    {
        int g2 = t >> 6, d2 = t & 63;
        float oo = aux[0 * 256 + g2 * 64 + d2] + aux[1 * 256 + g2 * 64 + d2]
                 + aux[2 * 256 + g2 * 64 + d2] + aux[3 * 256 + g2 * 64 + d2];
        g_pout[(size_t)(pbase + g2) * HD_ + d2] = oo;
    }
}

// ---------------- combine splits: plain sums ----------------
__global__ __launch_bounds__(256) void attn_combine_kernel()
{
    int kv = blockIdx.x, b = blockIdx.y;
    int t = threadIdx.x, g = t >> 6, d = t & 63;
    int base = (b * NKV_ + kv) * SPLIT_ * G_;

    float denom = 0.f, numer = 0.f;
#pragma unroll
    for (int i = 0; i < SPLIT_; i++) {
        denom += g_psum[base + i * G_ + g];
        numer += g_pout[(size_t)(base + i * G_ + g) * HD_ + d];
    }
    g_att[(size_t)b * (NH_ * HD_) + (kv * G_ + g) * HD_ + d] = numer / denom;
}

// ---------------- launch: kernel launches ONLY ----------------
extern "C" void kernel_launch(void* const* d_in, const int* in_sizes, int n_in,
                              void* d_out, int out_size)
{
    const float* hidden    = (const float*)d_in[0];
    const int*   positions = (const int*)  d_in[1];
    const int*   ctxlens   = (const int*)  d_in[2];
    // d_in[3] slot_mapping unused: phys(ctx-1) == slot, new k/v read directly
    const int*   btab      = (const int*)  d_in[4];
    const float* kc        = (const float*)d_in[5];
    const float* vc        = (const float*)d_in[6];
    const float* wqkv      = (const float*)d_in[7];
    const float* wout      = (const float*)d_in[8];
    const float* qlw       = (const float*)d_in[9];
    const float* klw       = (const float*)d_in[10];
    float* out = (float*)d_out;

    conv_a_hidden<<<B_ * HID_ / 256, 256>>>(hidden);
    gemm_mma_qkv<<<dim3(QKVN_ / 64, GSPL), 256>>>(wqkv);
    reduce_qkv_kernel<<<192, 256>>>();
    prep_kernel<<<B_, 256>>>(positions, qlw, klw);
    attn_split_kernel<<<dim3(NKV_, B_, SPLIT_), 256>>>(kc, vc, ctxlens, btab);
    attn_combine_kernel<<<dim3(NKV_, B_), 256>>>();
    conv_a_att<<<B_ * HID_ / 256, 256>>>();
    gemm_mma_out<<<dim3(HID_ / 64, GSPL), 256>>>(wout);
    reduce_out_kernel<<<128, 256>>>(out);
}

// round 16
// speedup vs baseline: 1.1947x; 1.0172x over previous
#include <cuda_runtime.h>
#include <cuda_bf16.h>
#include <cstdint>
#include <math.h>

// ---------------- problem constants ----------------
#define B_     64
#define HID_   2048
#define NH_    32
#define NKV_   8
#define HD_    64
#define G_     4          // NH/NKV
#define BS_    16
#define MAXB_  128
#define MAXKV_ 2048
#define QKVN_  3072       // NH*HD + 2*NKV*HD
#define SCALE_ 0.125f     // 64^-0.5
#define T_     32         // attention KV tile (positions)
#define SPLIT_ 8          // KV splits per (b, kv-head)
#define SCP_   264        // scs row stride (floats)
// GEMM tiling
#define ASTR   40         // A smem row stride (bf16)
#define BSTR   72         // B smem row stride (bf16)
#define GSPL   4          // GEMM K-splits

// ---------------- scratch: device globals only ----------------
__device__ float g_qkv [B_ * QKVN_];
__device__ float g_q   [B_ * NH_ * HD_];
__device__ float g_k   [B_ * NKV_ * HD_];
__device__ float g_psum[B_ * NKV_ * SPLIT_ * G_];
__device__ float g_pout[B_ * NKV_ * SPLIT_ * G_ * HD_];
__device__ float g_part[GSPL * B_ * QKVN_];       // GEMM split partials (3MB max)
__device__ __nv_bfloat16 g_ah[B_ * HID_];         // A hi [64][2048]
__device__ __nv_bfloat16 g_al[B_ * HID_];         // A lo

// ---------------- cp.async helpers ----------------
__device__ __forceinline__ void cpa16(void* smem, const void* gptr) {
    unsigned a = (unsigned)__cvta_generic_to_shared(smem);
    asm volatile("cp.async.cg.shared.global [%0], [%1], 16;\n" :: "r"(a), "l"(gptr));
}
__device__ __forceinline__ void cpa16z(void* smem, const void* gptr, bool v) {
    unsigned a = (unsigned)__cvta_generic_to_shared(smem);
    int sz = v ? 16 : 0;
    asm volatile("cp.async.cg.shared.global [%0], [%1], 16, %2;\n"
                 :: "r"(a), "l"(gptr), "r"(sz));
}
#define CPA_COMMIT() asm volatile("cp.async.commit_group;\n")
#define CPA_WAIT0()  asm volatile("cp.async.wait_group 0;\n")
#define CPA_WAIT1()  asm volatile("cp.async.wait_group 1;\n")

// ---------------- mma.sync helpers (sm_80+, arch-agnostic) ----------------
__device__ __forceinline__ void ldsm_x4(unsigned* r, unsigned addr) {
    asm volatile("ldmatrix.sync.aligned.m8n8.x4.shared.b16 {%0,%1,%2,%3}, [%4];"
                 : "=r"(r[0]), "=r"(r[1]), "=r"(r[2]), "=r"(r[3]) : "r"(addr));
}
__device__ __forceinline__ void ldsm_x4t(unsigned* r, unsigned addr) {
    asm volatile("ldmatrix.sync.aligned.m8n8.x4.trans.shared.b16 {%0,%1,%2,%3}, [%4];"
                 : "=r"(r[0]), "=r"(r[1]), "=r"(r[2]), "=r"(r[3]) : "r"(addr));
}
__device__ __forceinline__ void mma_bf16(float* c, const unsigned* a, const unsigned* b) {
    asm volatile(
        "mma.sync.aligned.m16n8k16.row.col.f32.bf16.bf16.f32 "
        "{%0,%1,%2,%3}, {%4,%5,%6,%7}, {%8,%9}, {%0,%1,%2,%3};"
        : "+f"(c[0]), "+f"(c[1]), "+f"(c[2]), "+f"(c[3])
        : "r"(a[0]), "r"(a[1]), "r"(a[2]), "r"(a[3]), "r"(b[0]), "r"(b[1]));
}

// ============================================================================
// A conversion for hidden (tiny: 64x2048)
// ============================================================================
__global__ void conv_a_hidden(const float* __restrict__ src) {
    int idx = blockIdx.x * 256 + threadIdx.x;
    float v = src[idx];
    __nv_bfloat16 h = __float2bfloat16(v);
    g_ah[idx] = h;
    g_al[idx] = __float2bfloat16(v - __bfloat162float(h));
}

// ============================================================================
// mma.sync GEMM with FUSED weight conversion (verified R15 kernel, unchanged)
// ============================================================================
__device__ __forceinline__ void gemm_mma_body(
    const float* __restrict__ w, int N, int kb0, int nkb, int split)
{
    __shared__ __nv_bfloat16 sAh[2][64 * ASTR], sAl[2][64 * ASTR];
    __shared__ __nv_bfloat16 sBh[32 * BSTR], sBl[32 * BSTR];

    int n0 = blockIdx.x * 64;
    int t = threadIdx.x, lane = t & 31, wid = t >> 5;
    int m0 = (wid & 3) * 16, wn0 = (wid >> 2) * 32;

    float acc[4][4];
#pragma unroll
    for (int j = 0; j < 4; j++)
#pragma unroll
        for (int i = 0; i < 4; i++) acc[j][i] = 0.f;

    int ar = t >> 2, ac = t & 3;
    int br = t >> 3, bc = (t & 7) * 8;

    int lg = lane >> 3, lr = lane & 7;
    int a_row = m0 + (lg & 1) * 8 + lr, a_colb = (lg >> 1) * 8;
    int b_krow = (lg & 1) * 8 + lr, b_ncol = (lg >> 1) * 8;

#define LOAD_A(buf, kb) do { \
    cpa16(&sAh[buf][ar * ASTR + ac * 8], g_ah + (size_t)ar * HID_ + (kb) + ac * 8); \
    cpa16(&sAl[buf][ar * ASTR + ac * 8], g_al + (size_t)ar * HID_ + (kb) + ac * 8); \
} while (0)

    float4 breg0, breg1;
#define LDGB(kb) do { \
    const float* wp = w + (size_t)((kb) + br) * N + n0 + bc; \
    breg0 = *(const float4*)wp; breg1 = *(const float4*)(wp + 4); \
} while (0)

    LOAD_A(0, kb0);
    CPA_COMMIT();
    LDGB(kb0);

    for (int kt = 0; kt < nkb; kt++) {
        int buf = kt & 1;
        if (kt + 1 < nkb) {
            LOAD_A(buf ^ 1, kb0 + (kt + 1) * 32);
            CPA_COMMIT();
            CPA_WAIT1();
        } else {
            CPA_WAIT0();
        }
        {
            float vals[8] = {breg0.x, breg0.y, breg0.z, breg0.w,
                             breg1.x, breg1.y, breg1.z, breg1.w};
            __nv_bfloat16 th[8], tl[8];
#pragma unroll
            for (int i = 0; i < 8; i++) {
                __nv_bfloat16 h = __float2bfloat16(vals[i]);
                th[i] = h;
                tl[i] = __float2bfloat16(vals[i] - __bfloat162float(h));
            }
            *(uint4*)&sBh[br * BSTR + bc] = *(uint4*)th;
            *(uint4*)&sBl[br * BSTR + bc] = *(uint4*)tl;
        }
        __syncthreads();
        if (kt + 1 < nkb) LDGB(kb0 + (kt + 1) * 32);
#pragma unroll
        for (int ks = 0; ks < 2; ks++) {
            unsigned ah4[4], al4[4], bh4[2][4], bl4[2][4];
            unsigned aoff = (unsigned)((a_row * ASTR + ks * 16 + a_colb) * 2);
            ldsm_x4(ah4, (unsigned)__cvta_generic_to_shared(&sAh[buf][0]) + aoff);
            ldsm_x4(al4, (unsigned)__cvta_generic_to_shared(&sAl[buf][0]) + aoff);
#pragma unroll
            for (int nh = 0; nh < 2; nh++) {
                unsigned boff = (unsigned)(((ks * 16 + b_krow) * BSTR + wn0 + nh * 16 + b_ncol) * 2);
                ldsm_x4t(bh4[nh], (unsigned)__cvta_generic_to_shared(&sBh[0]) + boff);
                ldsm_x4t(bl4[nh], (unsigned)__cvta_generic_to_shared(&sBl[0]) + boff);
            }
#pragma unroll
            for (int j = 0; j < 4; j++) {
                const unsigned* bh = &bh4[j >> 1][(j & 1) * 2];
                const unsigned* bl = &bl4[j >> 1][(j & 1) * 2];
                mma_bf16(acc[j], ah4, bh);
                mma_bf16(acc[j], al4, bh);
                mma_bf16(acc[j], ah4, bl);
            }
        }
        __syncthreads();
    }

    int gid = lane >> 2, q = lane & 3;
    float* dst = g_part + (size_t)split * (64 * N);
#pragma unroll
    for (int j = 0; j < 4; j++) {
        int col = n0 + wn0 + j * 8 + q * 2;
        int row0 = m0 + gid;
        *(float2*)&dst[(size_t)row0 * N + col]       = make_float2(acc[j][0], acc[j][1]);
        *(float2*)&dst[(size_t)(row0 + 8) * N + col] = make_float2(acc[j][2], acc[j][3]);
    }
#undef LOAD_A
#undef LDGB
}

__global__ __launch_bounds__(256) void gemm_mma_qkv(const float* __restrict__ w) {
    gemm_mma_body(w, QKVN_, blockIdx.y * (HID_ / GSPL), (HID_ / GSPL) / 32, blockIdx.y);
}
__global__ __launch_bounds__(256) void gemm_mma_out(const float* __restrict__ w) {
    gemm_mma_body(w, HID_, blockIdx.y * (HID_ / GSPL), (HID_ / GSPL) / 32, blockIdx.y);
}

// ---------------- reduce for OUT gemm (final output) ----------------
__global__ void reduce_out_kernel(float* __restrict__ out) {
    int i = blockIdx.x * 256 + threadIdx.x;    // n4 = 32768
    const float4* p = (const float4*)g_part;
    float4 s = p[i];
#pragma unroll
    for (int k = 1; k < GSPL; k++) {
        float4 v = p[(size_t)k * 32768 + i];
        s.x += v.x; s.y += v.y; s.z += v.z; s.w += v.w;
    }
    ((float4*)out)[i] = s;
}

// ============================================================================
// prep: FUSED qkv split-reduce + RMSNorm + RoPE. One CTA per batch row.
// ============================================================================
__global__ __launch_bounds__(256) void prep_kernel(
    const int* __restrict__ positions,
    const float* __restrict__ qw, const float* __restrict__ kw)
{
    __shared__ float row[QKVN_];         // 12 KB
    __shared__ float cs[32], sn[32];

    int b = blockIdx.x;
    int t = threadIdx.x, w = t >> 5, lane = t & 31;

    int pos = positions[b];
    if (t < 32) {
        double v = 1.0;
        if (t & 1)  v *= 0.6493816315762113;
        if (t & 2)  v *= 0.4216965034285822;
        if (t & 4)  v *= 0.17782794100389228;
        if (t & 8)  v *= 0.03162277660168379;
        if (t & 16) v *= 0.001;
        double ang = (double)pos * v;
        double k = floor(ang * 0.15915494309189535);
        float r = (float)(ang - k * 6.283185307179586);
        cs[t] = cosf(r);
        sn[t] = sinf(r);
    }

    // reduce 4 GEMM splits for this row: 768 float4s
    {
        const float4* p = (const float4*)g_part;
        int base = b * (QKVN_ / 4);
#pragma unroll
        for (int i = 0; i < 3; i++) {
            int idx = t + i * 256;                   // 0..767
            float4 s = p[base + idx];
#pragma unroll
            for (int k = 1; k < GSPL; k++) {
                float4 v = p[(size_t)k * (B_ * QKVN_ / 4) + base + idx];
                s.x += v.x; s.y += v.y; s.z += v.z; s.w += v.w;
            }
            ((float4*)row)[idx] = s;
            ((float4*)g_qkv)[base + idx] = s;        // attn needs V section
        }
    }
    __syncthreads();

    for (int h = w; h < NH_ + NKV_; h += 8) {
        bool isq = (h < NH_);
        const float* src = isq ? row + h * HD_ : row + NH_ * HD_ + (h - NH_) * HD_;
        float x1 = src[lane], x2 = src[lane + 32];
        float ss = x1 * x1 + x2 * x2;
#pragma unroll
        for (int o = 16; o; o >>= 1) ss += __shfl_xor_sync(0xffffffffu, ss, o);
        float inv = rsqrtf(ss * (1.f / 64.f) + 1e-5f);
        const float* lw = isq ? qw : kw;
        x1 *= inv * lw[lane];
        x2 *= inv * lw[lane + 32];
        float c = cs[lane], s = sn[lane];
        float y1 = x1 * c - x2 * s;
        float y2 = x2 * c + x1 * s;
        float* dst = isq ? g_q + ((size_t)b * NH_ + h) * HD_
                         : g_k + ((size_t)b * NKV_ + (h - NH_)) * HD_;
        dst[lane]      = y1;
        dst[lane + 32] = y2;
    }
}

// ============================================================================
// Split-KV attention (verified R15 kernel, unchanged)
// ============================================================================
__device__ __forceinline__ void tile_load(
    float* dst, const float* __restrict__ cache, const float* __restrict__ newrow,
    const int* sbt, int kv, int s0, int send, int ctx, int t)
{
    int c = t & 15;
#pragma unroll
    for (int r = 0; r < 2; r++) {
        int p = (t >> 4) + 16 * r;
        int s = s0 + p;
        bool v = (s < send);
        const float* src = cache;
        if (v) {
            if (s == ctx - 1) src = newrow + c * 4;
            else {
                int blk = sbt[s >> 4];
                src = cache + (((size_t)blk * BS_ + (s & 15)) * NKV_ + kv) * HD_ + c * 4;
            }
        }
        cpa16z(dst + p * 64 + c * 4, src, v);
    }
}

__global__ __launch_bounds__(256) void attn_split_kernel(
    const float* __restrict__ kc, const float* __restrict__ vc,
    const int* __restrict__ ctxlens, const int* __restrict__ btab)
{
    __shared__ float kt[3][T_ * 64];
    __shared__ float scs[G_ * SCP_];
    __shared__ float aux[1024];
    __shared__ float redm[8][4];
    __shared__ int   sbt[MAXB_];

    int kv = blockIdx.x, b = blockIdx.y, sp = blockIdx.z;
    int t = threadIdx.x, w = t >> 5, lane = t & 31;
    int ctx = ctxlens[b];
    ctx = ctx < 1 ? 1 : (ctx > MAXKV_ ? MAXKV_ : ctx);

    int chunk = (ctx + SPLIT_ - 1) / SPLIT_;
    int c0 = sp * chunk;
    int cn = min(chunk, ctx - c0);
    int pbase = ((b * NKV_ + kv) * SPLIT_ + sp) * G_;

    if (cn <= 0) {
        if (t < G_) g_psum[pbase + t] = 0.f;
        g_pout[(size_t)(pbase + (t >> 6)) * HD_ + (t & 63)] = 0.f;
        return;
    }

    if (t < MAXB_) sbt[t] = btab[b * MAXB_ + t];

    const float* knew_p = g_k + ((size_t)b * NKV_ + kv) * HD_;
    const float* vnew_p = g_qkv + (size_t)b * QKVN_ + NH_ * HD_ + NKV_ * HD_ + kv * HD_;

    int p = t >> 3, oct = t & 7;
    int g = (oct & 1) * 2 + ((oct >> 1) & 1);
    float4 qA[4], qB[4];
#pragma unroll
    for (int gg = 0; gg < 4; gg++) {
        const float* qrow = g_q + ((size_t)b * NH_ + kv * G_ + gg) * HD_;
        qA[gg] = *(const float4*)(qrow + oct * 4);
        qB[gg] = *(const float4*)(qrow + (oct + 8) * 4);
    }
    __syncthreads();

    int send = c0 + cn;
    int ntiles = (cn + T_ - 1) / T_;
    float sum_loc = 0.f;

    // ---- pass 1: probs = exp(q.K * scale) ----
#pragma unroll
    for (int i = 0; i < 2; i++) {
        if (i < ntiles) tile_load(kt[i], kc, knew_p, sbt, kv, c0 + i * T_, send, ctx, t);
        CPA_COMMIT();
    }
    for (int j = 0; j < ntiles; j++) {
        if (j < ntiles - 1) CPA_WAIT1(); else CPA_WAIT0();
        __syncthreads();
        if (j + 2 < ntiles) {
            tile_load(kt[(j + 2) % 3], kc, knew_p, sbt, kv, c0 + (j + 2) * T_, send, ctx, t);
            CPA_COMMIT();
        }
        const float* kb = kt[j % 3] + p * 64;
        float4 kA = *(const float4*)(kb + oct * 4);
        float4 kB = *(const float4*)(kb + (oct + 8) * 4);
        float dots[4];
#pragma unroll
        for (int gg = 0; gg < 4; gg++) {
            dots[gg] = qA[gg].x * kA.x + qA[gg].y * kA.y + qA[gg].z * kA.z + qA[gg].w * kA.w
                     + qB[gg].x * kB.x + qB[gg].y * kB.y + qB[gg].z * kB.z + qB[gg].w * kB.w;
        }
        bool b0 = oct & 1, b1 = oct & 2;
        float s1 = b0 ? dots[0] : dots[2];
        float r1 = __shfl_xor_sync(0xffffffffu, s1, 1);
        if (!b0) dots[0] += r1; else dots[2] += r1;
        float s2 = b0 ? dots[1] : dots[3];
        float r2 = __shfl_xor_sync(0xffffffffu, s2, 1);
        if (!b0) dots[1] += r2; else dots[3] += r2;
        float v0 = b0 ? dots[2] : dots[0];
        float v1 = b0 ? dots[3] : dots[1];
        float s3 = b1 ? v0 : v1;
        float r3 = __shfl_xor_sync(0xffffffffu, s3, 2);
        float v = (b1 ? v1 : v0) + r3;
        v += __shfl_xor_sync(0xffffffffu, v, 4);
        int sl = j * T_ + p;
        float pe = (sl < cn) ? __expf(v * SCALE_) : 0.f;
        if (oct < 4) scs[g * SCP_ + sl] = pe;
        sum_loc += pe;
    }
    sum_loc += __shfl_xor_sync(0xffffffffu, sum_loc, 8);
    sum_loc += __shfl_xor_sync(0xffffffffu, sum_loc, 16);
    if (lane < 4) redm[w][g] = sum_loc;
    __syncthreads();
    if (t < G_) {
        float ss = 0.f;
#pragma unroll
        for (int ww = 0; ww < 8; ww++) ss += redm[ww][t];
        g_psum[pbase + t] = ss;
    }
    __syncthreads();

    // ---- pass 2: out[g][d] = sum_s p[g][s] * V[s][d] ----
    int d = t & 63, sg = t >> 6;
    float oa0 = 0.f, oa1 = 0.f, oa2 = 0.f, oa3 = 0.f;
#pragma unroll
    for (int i = 0; i < 2; i++) {
        if (i < ntiles) tile_load(kt[i], vc, vnew_p, sbt, kv, c0 + i * T_, send, ctx, t);
        CPA_COMMIT();
    }
    for (int j = 0; j < ntiles; j++) {
        if (j < ntiles - 1) CPA_WAIT1(); else CPA_WAIT0();
        __syncthreads();
        if (j + 2 < ntiles) {
            tile_load(kt[(j + 2) % 3], vc, vnew_p, sbt, kv, c0 + (j + 2) * T_, send, ctx, t);
            CPA_COMMIT();
        }
        const float* vb = kt[j % 3];
        const float4* s4 = (const float4*)scs;
        int f0 = j * 8 + sg * 2;
#pragma unroll
        for (int i = 0; i < 2; i++) {
            float4 pa = s4[0 * 66 + f0 + i];
            float4 pb = s4[1 * 66 + f0 + i];
            float4 pc = s4[2 * 66 + f0 + i];
            float4 pd = s4[3 * 66 + f0 + i];
            int sb = (sg * 8 + i * 4) * 64 + d;
            float w0 = vb[sb], w1 = vb[sb + 64], w2 = vb[sb + 128], w3 = vb[sb + 192];
            oa0 += pa.x * w0 + pa.y * w1 + pa.z * w2 + pa.w * w3;
            oa1 += pb.x * w0 + pb.y * w1 + pb.z * w2 + pb.w * w3;
            oa2 += pc.x * w0 + pc.y * w1 + pc.z * w2 + pc.w * w3;
            oa3 += pd.x * w0 + pd.y * w1 + pd.z * w2 + pd.w * w3;
        }
    }
    __syncthreads();
    aux[sg * 256 + 0 * 64 + d] = oa0;
    aux[sg * 256 + 1 * 64 + d] = oa1;
    aux[sg * 256 + 2 * 64 + d] = oa2;
    aux[sg * 256 + 3 * 64 + d] = oa3;
    __syncthreads();
    {
        int g2 = t >> 6, d2 = t & 63;
        float oo = aux[0 * 256 + g2 * 64 + d2] + aux[1 * 256 + g2 * 64 + d2]
                 + aux[2 * 256 + g2 * 64 + d2] + aux[3 * 256 + g2 * 64 + d2];
        g_pout[(size_t)(pbase + g2) * HD_ + d2] = oo;
    }
}

// ---------------- combine splits + FUSED bf16 hi/lo split of output --------
__global__ __launch_bounds__(256) void attn_combine_kernel()
{
    int kv = blockIdx.x, b = blockIdx.y;
    int t = threadIdx.x, g = t >> 6, d = t & 63;
    int base = (b * NKV_ + kv) * SPLIT_ * G_;

    float denom = 0.f, numer = 0.f;
#pragma unroll
    for (int i = 0; i < SPLIT_; i++) {
        denom += g_psum[base + i * G_ + g];
        numer += g_pout[(size_t)(base + i * G_ + g) * HD_ + d];
    }
    float oo = numer / denom;
    int idx = b * HID_ + (kv * G_ + g) * HD_ + d;   // row-major [64][2048]
    __nv_bfloat16 h = __float2bfloat16(oo);
    g_ah[idx] = h;
    g_al[idx] = __float2bfloat16(oo - __bfloat162float(h));
}

// ---------------- launch: kernel launches ONLY ----------------
extern "C" void kernel_launch(void* const* d_in, const int* in_sizes, int n_in,
                              void* d_out, int out_size)
{
    const float* hidden    = (const float*)d_in[0];
    const int*   positions = (const int*)  d_in[1];
    const int*   ctxlens   = (const int*)  d_in[2];
    // d_in[3] slot_mapping unused: phys(ctx-1) == slot, new k/v read directly
    const int*   btab      = (const int*)  d_in[4];
    const float* kc        = (const float*)d_in[5];
    const float* vc        = (const float*)d_in[6];
    const float* wqkv      = (const float*)d_in[7];
    const float* wout      = (const float*)d_in[8];
    const float* qlw       = (const float*)d_in[9];
    const float* klw       = (const float*)d_in[10];
    float* out = (float*)d_out;

    conv_a_hidden<<<B_ * HID_ / 256, 256>>>(hidden);
    gemm_mma_qkv<<<dim3(QKVN_ / 64, GSPL), 256>>>(wqkv);
    prep_kernel<<<B_, 256>>>(positions, qlw, klw);
    attn_split_kernel<<<dim3(NKV_, B_, SPLIT_), 256>>>(kc, vc, ctxlens, btab);
    attn_combine_kernel<<<dim3(NKV_, B_), 256>>>();
    gemm_mma_out<<<dim3(HID_ / 64, GSPL), 256>>>(wout);
    reduce_out_kernel<<<128, 256>>>(out);
}